// round 14
// baseline (speedup 1.0000x reference)
#include <cuda_runtime.h>
#include <math.h>

#define B_NO   8
#define T_LEN  10000
#define E_NUM  1000
#define I_NUM  250
#define SUB_NO 8
#define HID_NO 16
#define CBAS   30
#define T_NO   200

// output layout: final | sub_out | C_syn_e | C_syn_i
#define FINAL_OFF  0
#define SUBOUT_OFF (B_NO * T_LEN)                       // 80000
#define CE_OFF     (SUBOUT_OFF + B_NO * T_LEN * SUB_NO) // 720000
#define CI_OFF     (CE_OFF + SUB_NO * E_NUM)            // 728000

// ---------------- device scratch ----------------
__device__ __align__(16) float g_kern_e[SUB_NO * T_NO * HID_NO];  // [s][tau][h]
__device__ __align__(16) float g_kern_i[SUB_NO * T_NO * HID_NO];
__device__ float g_syn_e[B_NO * SUB_NO * T_LEN];                  // [b][s][t]
__device__ float g_syn_i[B_NO * SUB_NO * T_LEN];
// scaled C in s-pair layout: g_C2e[sp*1024 + e] = {C[2sp][e], C[2sp+1][e]} * exp(scale)
__device__ __align__(16) float2 g_C2e[4 * 1024];   // e-padded with zeros
__device__ __align__(16) float2 g_C2i[4 * 256];

// ---------------- helpers ----------------
__device__ __forceinline__ float2 ffma2(float2 a, float2 b, float2 c) {
    union U { float2 f; unsigned long long u; };
    U A, B, C, D;
    A.f = a; B.f = b; C.f = c;
    asm("fma.rn.f32x2 %0, %1, %2, %3;" : "=l"(D.u) : "l"(A.u), "l"(B.u), "l"(C.u));
    return D.f;
}

__device__ __forceinline__ float tanh_fast(float x) {
    float e = __expf(2.0f * x);
    return 1.0f - __fdividef(2.0f, e + 1.0f);
}

__device__ __forceinline__ float2 shfl_xor_f2(float2 v, int m) {
    union { float2 f; double d; } u;
    u.f = v;
    u.d = __shfl_xor_sync(0xffffffffu, u.d, m);
    return u.f;
}

// Halving-tree reduction of 16 float2 values across 32 lanes.
// On exit lane L holds (in a[0]) the full sum of value index (L & 15).
__device__ __forceinline__ void tree_reduce16(float2 (&a)[16], int lane) {
#pragma unroll
    for (int v = 0; v < 16; ++v) {
        float2 o = shfl_xor_f2(a[v], 16);
        a[v].x += o.x; a[v].y += o.y;
    }
#pragma unroll
    for (int v = 0; v < 8; ++v) {
        float2 send = (lane & 8) ? a[v] : a[v + 8];
        float2 o = shfl_xor_f2(send, 8);
        float2 keep = (lane & 8) ? a[v + 8] : a[v];
        a[v] = make_float2(keep.x + o.x, keep.y + o.y);
    }
#pragma unroll
    for (int v = 0; v < 4; ++v) {
        float2 send = (lane & 4) ? a[v] : a[v + 4];
        float2 o = shfl_xor_f2(send, 4);
        float2 keep = (lane & 4) ? a[v + 4] : a[v];
        a[v] = make_float2(keep.x + o.x, keep.y + o.y);
    }
#pragma unroll
    for (int v = 0; v < 2; ++v) {
        float2 send = (lane & 2) ? a[v] : a[v + 2];
        float2 o = shfl_xor_f2(send, 2);
        float2 keep = (lane & 2) ? a[v + 2] : a[v];
        a[v] = make_float2(keep.x + o.x, keep.y + o.y);
    }
    {
        float2 send = (lane & 1) ? a[0] : a[1];
        float2 o = shfl_xor_f2(send, 1);
        float2 keep = (lane & 1) ? a[1] : a[0];
        a[0] = make_float2(keep.x + o.x, keep.y + o.y);
    }
}

// ---------------- K0: softmax + scaled pair-layout copies (+padding zero) --------
__global__ void softmax_kernel(const float* __restrict__ Cer,
                               const float* __restrict__ Cir,
                               const float* __restrict__ Es,
                               const float* __restrict__ Is,
                               float* __restrict__ out) {
    int idx = blockIdx.x * blockDim.x + threadIdx.x;
    if (idx < E_NUM) {
        float u[SUB_NO], p[SUB_NO];
        float m = -1e30f;
#pragma unroll
        for (int s = 0; s < SUB_NO; ++s) { u[s] = Cer[s * E_NUM + idx] * 10000.0f; m = fmaxf(m, u[s]); }
        float sum = 0.0f;
#pragma unroll
        for (int s = 0; s < SUB_NO; ++s) { p[s] = expf(u[s] - m); sum += p[s]; }
        float inv = 1.0f / sum;
        float sc  = expf(Es[idx]);
        float v[SUB_NO];
#pragma unroll
        for (int s = 0; s < SUB_NO; ++s) {
            v[s] = p[s] * inv;
            out[CE_OFF + s * E_NUM + idx] = v[s];
        }
#pragma unroll
        for (int sp = 0; sp < 4; ++sp)
            g_C2e[sp * 1024 + idx] = make_float2(v[2 * sp] * sc, v[2 * sp + 1] * sc);
    } else if (idx < E_NUM + I_NUM) {
        int j = idx - E_NUM;
        float u[SUB_NO], p[SUB_NO];
        float m = -1e30f;
#pragma unroll
        for (int s = 0; s < SUB_NO; ++s) { u[s] = Cir[s * I_NUM + j] * 10000.0f; m = fmaxf(m, u[s]); }
        float sum = 0.0f;
#pragma unroll
        for (int s = 0; s < SUB_NO; ++s) { p[s] = expf(u[s] - m); sum += p[s]; }
        float inv = 1.0f / sum;
        float sc  = expf(Is[j]);
        float v[SUB_NO];
#pragma unroll
        for (int s = 0; s < SUB_NO; ++s) {
            v[s] = p[s] * inv;
            out[CI_OFF + s * I_NUM + j] = v[s];
        }
#pragma unroll
        for (int sp = 0; sp < 4; ++sp)
            g_C2i[sp * 256 + j] = make_float2(v[2 * sp] * sc, v[2 * sp + 1] * sc);
    } else if (idx < E_NUM + I_NUM + 24) {       // zero-pad C_e rows [1000,1024)
        int row = 1000 + (idx - (E_NUM + I_NUM));
#pragma unroll
        for (int sp = 0; sp < 4; ++sp) g_C2e[sp * 1024 + row] = make_float2(0.f, 0.f);
    } else if (idx < E_NUM + I_NUM + 24 + 6) {   // zero-pad C_i rows [250,256)
        int row = 250 + (idx - (E_NUM + I_NUM + 24));
#pragma unroll
        for (int sp = 0; sp < 4; ++sp) g_C2i[sp * 256 + row] = make_float2(0.f, 0.f);
    }
}

// ---------------- K1: temporal kernels from cosine basis ----------------
__global__ void kern_kernel(const float* __restrict__ W_e,
                            const float* __restrict__ W_i) {
    __shared__ float bas[CBAS];
    int tau = blockIdx.x;
    if (threadIdx.x < CBAS) {
        double phi = 0.5 * M_PI * (double)threadIdx.x;
        double raw = 7.5 * log((double)tau + 1.0 + 1e-7);
        double v = 0.0;
        if (raw >= phi - M_PI && raw <= phi + M_PI)
            v = 0.5 * cos(raw - phi) + 0.5;
        bas[threadIdx.x] = (float)v;
    }
    __syncthreads();
    int r = threadIdx.x;             // 0..127
    float ae = 0.0f, ai = 0.0f;
#pragma unroll
    for (int c = 0; c < CBAS; ++c) {
        ae = fmaf(W_e[r * CBAS + c], bas[c], ae);
        ai = fmaf(W_i[r * CBAS + c], bas[c], ai);
    }
    int s = r >> 4, h = r & 15;
    g_kern_e[(s * T_NO + tau) * HID_NO + h] = ae;
    g_kern_i[(s * T_NO + tau) * HID_NO + h] = ai;
}

// ---------------- K2: synapse pooling (barrier-free, lanes-over-e) ----------------
// warp tile = 4 t; block = 8 warps = 32 t; grid (313, 8)
__global__ void __launch_bounds__(256, 3)
pool_kernel(const float* __restrict__ S_e, const float* __restrict__ S_i) {
    __shared__ float2 sC2e[4 * 1024];   // 32KB
    __shared__ float2 sC2i[4 * 256];    //  8KB

    int tid = threadIdx.x, lane = tid & 31, warp = tid >> 5;
    for (int i = tid; i < 2048; i += 256)
        ((float4*)sC2e)[i] = ((const float4*)g_C2e)[i];
    for (int i = tid; i < 512; i += 256)
        ((float4*)sC2i)[i] = ((const float4*)g_C2i)[i];
    __syncthreads();

    int b = blockIdx.y;
    int t0 = blockIdx.x * 32 + warp * 4;
    const float* Se = S_e + (size_t)b * T_LEN * E_NUM;
    const float* Si = S_i + (size_t)b * T_LEN * I_NUM;

    float2 a[16];

    // ================= E =================
#pragma unroll
    for (int v = 0; v < 16; ++v) a[v] = make_float2(0.f, 0.f);

#pragma unroll 2
    for (int kk = 0; kk < 1024; kk += 64) {
        int eA = kk + lane, eB = kk + 32 + lane;
        float xA[4], xB[4];
#pragma unroll
        for (int i = 0; i < 4; ++i) {
            int t = t0 + i;
            bool tv = (t < T_LEN);
            const float* row = Se + (size_t)t * E_NUM;
            xA[i] = (tv && eA < E_NUM) ? __ldg(row + eA) : 0.f;
            xB[i] = (tv && eB < E_NUM) ? __ldg(row + eB) : 0.f;
        }
        float2 cA[4], cB[4];
#pragma unroll
        for (int sp = 0; sp < 4; ++sp) {
            cA[sp] = sC2e[sp * 1024 + eA];
            cB[sp] = sC2e[sp * 1024 + eB];
        }
#pragma unroll
        for (int i = 0; i < 4; ++i) {
            float2 vA = make_float2(xA[i], xA[i]);
            float2 vB = make_float2(xB[i], xB[i]);
#pragma unroll
            for (int sp = 0; sp < 4; ++sp) {
                a[i * 4 + sp] = ffma2(cA[sp], vA, a[i * 4 + sp]);
                a[i * 4 + sp] = ffma2(cB[sp], vB, a[i * 4 + sp]);
            }
        }
    }
    tree_reduce16(a, lane);
    if (lane < 16) {
        int i = (lane >> 2) & 3, sp = lane & 3;
        int t = t0 + i;
        if (t < T_LEN) {
            float* d = &g_syn_e[(b * SUB_NO) * T_LEN];
            d[(2 * sp) * T_LEN + t]     = a[0].x;
            d[(2 * sp + 1) * T_LEN + t] = a[0].y;
        }
    }

    // ================= I =================
#pragma unroll
    for (int v = 0; v < 16; ++v) a[v] = make_float2(0.f, 0.f);

#pragma unroll 2
    for (int kk = 0; kk < 256; kk += 64) {
        int eA = kk + lane, eB = kk + 32 + lane;
        float xA[4], xB[4];
#pragma unroll
        for (int i = 0; i < 4; ++i) {
            int t = t0 + i;
            bool tv = (t < T_LEN);
            const float* row = Si + (size_t)t * I_NUM;
            xA[i] = (tv && eA < I_NUM) ? __ldg(row + eA) : 0.f;
            xB[i] = (tv && eB < I_NUM) ? __ldg(row + eB) : 0.f;
        }
        float2 cA[4], cB[4];
#pragma unroll
        for (int sp = 0; sp < 4; ++sp) {
            cA[sp] = sC2i[sp * 256 + eA];
            cB[sp] = sC2i[sp * 256 + eB];
        }
#pragma unroll
        for (int i = 0; i < 4; ++i) {
            float2 vA = make_float2(xA[i], xA[i]);
            float2 vB = make_float2(xB[i], xB[i]);
#pragma unroll
            for (int sp = 0; sp < 4; ++sp) {
                a[i * 4 + sp] = ffma2(cA[sp], vA, a[i * 4 + sp]);
                a[i * 4 + sp] = ffma2(cB[sp], vB, a[i * 4 + sp]);
            }
        }
    }
    tree_reduce16(a, lane);
    if (lane < 16) {
        int i = (lane >> 2) & 3, sp = lane & 3;
        int t = t0 + i;
        if (t < T_LEN) {
            float* d = &g_syn_i[(b * SUB_NO) * T_LEN];
            d[(2 * sp) * T_LEN + t]     = a[0].x;
            d[(2 * sp + 1) * T_LEN + t] = a[0].y;
        }
    }
}

// ---------------- K3: causal conv + tanh + readout (sliding-window x) ------------
// Thread owns consecutive t-pair {t0+2tid, t0+2tid+1}. x staged in even/odd shared
// arrays so the per-tau "new" load is stride-1 conflict-free (parity uniform per tau).
#define TC 512
#define XW (TC + T_NO)   // 712
#define NEV (XW / 2)     // 356 even slots
#define NOD (XW / 2 + 1) // 357: odd slots shifted +1 (arr[0] = pad)

__global__ void __launch_bounds__(256, 3)
conv_kernel(const float* __restrict__ W2,
            const float* __restrict__ b1,
            float* __restrict__ out) {
    __shared__ __align__(16) float4 sKe[T_NO * 4];   // [tau][4 float4] = 16 h
    __shared__ __align__(16) float4 sKi[T_NO * 4];
    __shared__ float sXeE[NEV], sXeO[NOD];
    __shared__ float sXiE[NEV], sXiO[NOD];
    __shared__ float sEw2[HID_NO], sB1[HID_NO];

    int tid = threadIdx.x;
    int bs = blockIdx.y;
    int b = bs >> 3, s = bs & 7;
    int t0 = blockIdx.x * TC;

    const float4* ge = (const float4*)g_kern_e + s * (T_NO * 4);
    const float4* gi = (const float4*)g_kern_i + s * (T_NO * 4);
    for (int idx = tid; idx < T_NO * 4; idx += 256) {
        sKe[idx] = ge[idx];
        sKi[idx] = gi[idx];
    }
    // fill x: local offset idx covers t = t0-199+idx
    for (int idx = tid; idx < XW; idx += 256) {
        int g = t0 - (T_NO - 1) + idx;
        bool ok = (g >= 0) && (g < T_LEN);
        float ve = ok ? g_syn_e[(b * SUB_NO + s) * T_LEN + g] : 0.0f;
        float vi = ok ? g_syn_i[(b * SUB_NO + s) * T_LEN + g] : 0.0f;
        if (idx & 1) { sXeO[(idx >> 1) + 1] = ve; sXiO[(idx >> 1) + 1] = vi; }
        else         { sXeE[idx >> 1] = ve;       sXiE[idx >> 1] = vi; }
    }
    if (tid == 0) { sXeO[0] = 0.f; sXiO[0] = 0.f; }
    if (tid < HID_NO) {
        sEw2[tid] = expf(W2[s * HID_NO + tid]);
        sB1[tid]  = b1[s * HID_NO + tid];
    }
    __syncthreads();

    float2 accL[8], accH[8];   // L: t=t0+2tid, H: t=t0+2tid+1
#pragma unroll
    for (int hp = 0; hp < 8; ++hp) {
        accL[hp] = make_float2(0.0f, 0.0f);
        accH[hp] = make_float2(0.0f, 0.0f);
    }

    // window init: hi = x(2tid+200) even -> E[tid+100]; lo = x(2tid+199) odd -> Oarr[tid+100]
    float xeH = sXeE[tid + 100], xeL = sXeO[tid + 100];
    float xiH = sXiE[tid + 100], xiL = sXiO[tid + 100];

#pragma unroll 2
    for (int tau = 0; tau < T_NO; tau += 2) {
        // ---- tau (even): hi=xeH/xiH, lo=xeL/xiL ----
        {
            float2 vH = make_float2(xeH, xeH), vL = make_float2(xeL, xeL);
#pragma unroll
            for (int q = 0; q < 4; ++q) {
                float4 ke = sKe[tau * 4 + q];
                float2 kA = make_float2(ke.x, ke.y), kB = make_float2(ke.z, ke.w);
                accH[2*q]   = ffma2(kA, vH, accH[2*q]);
                accH[2*q+1] = ffma2(kB, vH, accH[2*q+1]);
                accL[2*q]   = ffma2(kA, vL, accL[2*q]);
                accL[2*q+1] = ffma2(kB, vL, accL[2*q+1]);
            }
            float2 wH = make_float2(xiH, xiH), wL = make_float2(xiL, xiL);
#pragma unroll
            for (int q = 0; q < 4; ++q) {
                float4 ki = sKi[tau * 4 + q];
                float2 kA = make_float2(ki.x, ki.y), kB = make_float2(ki.z, ki.w);
                accH[2*q]   = ffma2(kA, wH, accH[2*q]);
                accH[2*q+1] = ffma2(kB, wH, accH[2*q+1]);
                accL[2*q]   = ffma2(kA, wL, accL[2*q]);
                accL[2*q+1] = ffma2(kB, wL, accL[2*q+1]);
            }
        }
        // new value for tau+1 low slot: x(2tid+198-tau) even -> E[tid+99-tau/2]
        int base = tid + 99 - (tau >> 1);
        float xeN = sXeE[base];
        float xiN = sXiE[base];
        // ---- tau+1: hi = old lo, lo = new ----
        {
            float2 vH = make_float2(xeL, xeL), vL = make_float2(xeN, xeN);
#pragma unroll
            for (int q = 0; q < 4; ++q) {
                float4 ke = sKe[(tau + 1) * 4 + q];
                float2 kA = make_float2(ke.x, ke.y), kB = make_float2(ke.z, ke.w);
                accH[2*q]   = ffma2(kA, vH, accH[2*q]);
                accH[2*q+1] = ffma2(kB, vH, accH[2*q+1]);
                accL[2*q]   = ffma2(kA, vL, accL[2*q]);
                accL[2*q+1] = ffma2(kB, vL, accL[2*q+1]);
            }
            float2 wH = make_float2(xiL, xiL), wL = make_float2(xiN, xiN);
#pragma unroll
            for (int q = 0; q < 4; ++q) {
                float4 ki = sKi[(tau + 1) * 4 + q];
                float2 kA = make_float2(ki.x, ki.y), kB = make_float2(ki.z, ki.w);
                accH[2*q]   = ffma2(kA, wH, accH[2*q]);
                accH[2*q+1] = ffma2(kB, wH, accH[2*q+1]);
                accL[2*q]   = ffma2(kA, wL, accL[2*q]);
                accL[2*q+1] = ffma2(kB, wL, accL[2*q+1]);
            }
        }
        // advance window for tau+2: hi = xN; lo = x(2tid+197-tau) odd -> Oarr[tid+99-tau/2]
        xeH = xeN; xiH = xiN;
        xeL = sXeO[base];
        xiL = sXiO[base];
    }

    // epilogue: tanh + positive readout -> sub_out[b, t, s]
    {
        int t = t0 + 2 * tid;
        if (t < T_LEN) {
            float so = 0.0f;
#pragma unroll
            for (int hp = 0; hp < 8; ++hp) {
                so = fmaf(sEw2[2 * hp],     tanh_fast(accL[hp].x + sB1[2 * hp]),     so);
                so = fmaf(sEw2[2 * hp + 1], tanh_fast(accL[hp].y + sB1[2 * hp + 1]), so);
            }
            out[SUBOUT_OFF + (size_t)(b * T_LEN + t) * SUB_NO + s] = so;
        }
    }
    {
        int t = t0 + 2 * tid + 1;
        if (t < T_LEN) {
            float so = 0.0f;
#pragma unroll
            for (int hp = 0; hp < 8; ++hp) {
                so = fmaf(sEw2[2 * hp],     tanh_fast(accH[hp].x + sB1[2 * hp]),     so);
                so = fmaf(sEw2[2 * hp + 1], tanh_fast(accH[hp].y + sB1[2 * hp + 1]), so);
            }
            out[SUBOUT_OFF + (size_t)(b * T_LEN + t) * SUB_NO + s] = so;
        }
    }
}

// ---------------- K4: final = sum_s sub_out + V_o ----------------
__global__ void final_kernel(const float* __restrict__ V_o, float* __restrict__ out) {
    int idx = blockIdx.x * blockDim.x + threadIdx.x;
    if (idx >= B_NO * T_LEN) return;
    const float4* p = (const float4*)&out[SUBOUT_OFF + (size_t)idx * SUB_NO];
    float4 a = p[0], c = p[1];
    out[FINAL_OFF + idx] = V_o[0] + ((a.x + a.y) + (a.z + a.w)) + ((c.x + c.y) + (c.z + c.w));
}

// ---------------- launch ----------------
extern "C" void kernel_launch(void* const* d_in, const int* in_sizes, int n_in,
                              void* d_out, int out_size) {
    (void)in_sizes; (void)n_in; (void)out_size;
    const float* S_e   = (const float*)d_in[0];
    const float* S_i   = (const float*)d_in[1];
    const float* Es    = (const float*)d_in[2];
    const float* Is    = (const float*)d_in[3];
    const float* W_e   = (const float*)d_in[4];
    const float* W_i   = (const float*)d_in[5];
    const float* W2    = (const float*)d_in[6];
    const float* b1    = (const float*)d_in[7];
    const float* Cer   = (const float*)d_in[8];
    const float* Cir   = (const float*)d_in[9];
    const float* V_o   = (const float*)d_in[10];
    float* out = (float*)d_out;

    softmax_kernel<<<(E_NUM + I_NUM + 30 + 255) / 256, 256>>>(Cer, Cir, Es, Is, out);
    kern_kernel<<<T_NO, 128>>>(W_e, W_i);

    dim3 pg((T_LEN + 31) / 32, B_NO);                  // 313 x 8 = 2504 blocks
    pool_kernel<<<pg, 256>>>(S_e, S_i);

    dim3 cg((T_LEN + TC - 1) / TC, B_NO * SUB_NO);     // 20 x 64
    conv_kernel<<<cg, 256>>>(W2, b1, out);

    final_kernel<<<(B_NO * T_LEN + 255) / 256, 256>>>(V_o, out);
}